// round 1
// baseline (speedup 1.0000x reference)
#include <cuda_runtime.h>

// ---------------------------------------------------------------------------
// Scratch (allocation-free: __device__ globals)
// ---------------------------------------------------------------------------
__device__ float g_qkv[8 * 512 * 3072];   // [B*S, 3D] fused qkv output
__device__ float g_attn[8 * 512 * 1024];  // [B*S, D] merged-head attention out

// ---------------------------------------------------------------------------
// SGEMM: C[M,N] = A[M,K] @ B[K,N] + bias[N]   (row-major, M%128==N%128==K%8==0)
// 128x128 block tile, 256 threads, 8x8 per-thread microtile (split 64/64).
// ---------------------------------------------------------------------------
__global__ void __launch_bounds__(256) sgemm_bias_kernel(
    const float* __restrict__ A, const float* __restrict__ B,
    const float* __restrict__ bias, float* __restrict__ C,
    int M, int N, int K)
{
    __shared__ float As[8][128];   // A tile transposed: [k][m]
    __shared__ float Bs[8][128];   // B tile: [k][n]

    const int tid = threadIdx.x;
    const int tx  = tid & 15;      // 16 thread cols
    const int ty  = tid >> 4;      // 16 thread rows
    const int bx  = blockIdx.x;    // N tile
    const int by  = blockIdx.y;    // M tile

    const int arow = tid >> 1;            // 0..127
    const int acol = (tid & 1) << 2;      // 0 or 4
    const int brow = tid >> 5;            // 0..7
    const int bcol = (tid & 31) << 2;     // 0..124

    const float* Aptr = A + (size_t)(by * 128 + arow) * K + acol;
    const float* Bptr = B + (size_t)brow * N + bx * 128 + bcol;

    float acc[8][8];
    #pragma unroll
    for (int i = 0; i < 8; i++)
        #pragma unroll
        for (int j = 0; j < 8; j++) acc[i][j] = 0.f;

    for (int k0 = 0; k0 < K; k0 += 8) {
        float4 av = *(const float4*)(Aptr + k0);
        As[acol + 0][arow] = av.x;
        As[acol + 1][arow] = av.y;
        As[acol + 2][arow] = av.z;
        As[acol + 3][arow] = av.w;
        *(float4*)&Bs[brow][bcol] = *(const float4*)(Bptr + (size_t)k0 * N);
        __syncthreads();

        #pragma unroll
        for (int kk = 0; kk < 8; kk++) {
            float ar[8], br[8];
            *(float4*)&ar[0] = *(const float4*)&As[kk][ty * 4];
            *(float4*)&ar[4] = *(const float4*)&As[kk][64 + ty * 4];
            *(float4*)&br[0] = *(const float4*)&Bs[kk][tx * 4];
            *(float4*)&br[4] = *(const float4*)&Bs[kk][64 + tx * 4];
            #pragma unroll
            for (int i = 0; i < 8; i++)
                #pragma unroll
                for (int j = 0; j < 8; j++)
                    acc[i][j] += ar[i] * br[j];
        }
        __syncthreads();
    }

    #pragma unroll
    for (int ih = 0; ih < 2; ih++) {
        #pragma unroll
        for (int i = 0; i < 4; i++) {
            const int row = by * 128 + ih * 64 + ty * 4 + i;
            #pragma unroll
            for (int jh = 0; jh < 2; jh++) {
                const int col = bx * 128 + jh * 64 + tx * 4;
                float4 o;
                o.x = acc[ih * 4 + i][jh * 4 + 0] + bias[col + 0];
                o.y = acc[ih * 4 + i][jh * 4 + 1] + bias[col + 1];
                o.z = acc[ih * 4 + i][jh * 4 + 2] + bias[col + 2];
                o.w = acc[ih * 4 + i][jh * 4 + 3] + bias[col + 3];
                *(float4*)&C[(size_t)row * N + col] = o;
            }
        }
    }
}

// ---------------------------------------------------------------------------
// Fused causal attention (flash-style online softmax), fp32.
// grid = (S/64, H, B); 128 threads; 64-query tile per block.
// Thread (tx 0..15, ty 0..7): 8 q-rows x 4 k-cols of scores, 8x4 of output.
// K and V tiles share one smem buffer (K phase transposed [d][k], V phase [k][d]).
// ---------------------------------------------------------------------------
__global__ void __launch_bounds__(128) attention_kernel(
    const float* __restrict__ qkv, const float* __restrict__ mask,
    float* __restrict__ out)
{
    const int qt  = blockIdx.x;   // query tile 0..7
    const int h   = blockIdx.y;   // head 0..15
    const int b   = blockIdx.z;   // batch 0..7
    const int tid = threadIdx.x;
    const int tx  = tid & 15;     // k dim, 4 cols each
    const int ty  = tid >> 4;     // q dim, 8 rows each

    __shared__ float Qt[64][64];  // Q transposed: [d][q]
    __shared__ float KV[64][64];  // K phase: [d][k]; V phase: [k][d]
    __shared__ float Ps[64][64];  // probabilities [q][k]

    const int q0 = qt * 64;
    const float* qbase = qkv + (size_t)(b * 512) * 3072 + h * 64;
    const float* kbase = qbase + 1024;
    const float* vbase = qbase + 2048;

    // Load Q tile transposed
    for (int t = tid; t < 64 * 16; t += 128) {
        const int r = t >> 4;
        const int c = (t & 15) << 2;
        float4 v = *(const float4*)(qbase + (size_t)(q0 + r) * 3072 + c);
        Qt[c + 0][r] = v.x; Qt[c + 1][r] = v.y;
        Qt[c + 2][r] = v.z; Qt[c + 3][r] = v.w;
    }

    float acc[8][4];
    float mrun[8], lrun[8];
    #pragma unroll
    for (int i = 0; i < 8; i++) {
        mrun[i] = -1e30f;
        lrun[i] = 0.f;
        #pragma unroll
        for (int j = 0; j < 4; j++) acc[i][j] = 0.f;
    }

    for (int kt = 0; kt <= qt; kt++) {   // causal: skip upper tiles
        const int k0 = kt * 64;

        __syncthreads();  // previous iter done reading KV/Ps
        // Load K tile transposed: KV[d][k]
        for (int t = tid; t < 64 * 16; t += 128) {
            const int r = t >> 4;
            const int c = (t & 15) << 2;
            float4 v = *(const float4*)(kbase + (size_t)(k0 + r) * 3072 + c);
            KV[c + 0][r] = v.x; KV[c + 1][r] = v.y;
            KV[c + 2][r] = v.z; KV[c + 3][r] = v.w;
        }
        __syncthreads();

        // Scores: s[i][j] = sum_d Q[q][d] * K[k][d]
        float s[8][4];
        #pragma unroll
        for (int i = 0; i < 8; i++)
            #pragma unroll
            for (int j = 0; j < 4; j++) s[i][j] = 0.f;

        #pragma unroll 8
        for (int d = 0; d < 64; d++) {
            float qr[8];
            *(float4*)&qr[0] = *(const float4*)&Qt[d][ty * 8];
            *(float4*)&qr[4] = *(const float4*)&Qt[d][ty * 8 + 4];
            const float4 kv = *(const float4*)&KV[d][tx * 4];
            #pragma unroll
            for (int i = 0; i < 8; i++) {
                s[i][0] += qr[i] * kv.x;
                s[i][1] += qr[i] * kv.y;
                s[i][2] += qr[i] * kv.z;
                s[i][3] += qr[i] * kv.w;
            }
        }
        __syncthreads();  // all threads done reading K tile

        // Load V tile: KV[k][d] (overlaps register softmax below)
        for (int t = tid; t < 64 * 16; t += 128) {
            const int r = t >> 4;
            const int c = (t & 15) << 2;
            *(float4*)&KV[r][c] =
                *(const float4*)(vbase + (size_t)(k0 + r) * 3072 + c);
        }

        // Mask values for this thread's 4 key columns
        float mk[4];
        #pragma unroll
        for (int j = 0; j < 4; j++)
            mk[j] = mask[b * 512 + k0 + tx * 4 + j];

        // Scale + mask + online softmax
        #pragma unroll
        for (int i = 0; i < 8; i++) {
            const int qg = q0 + ty * 8 + i;
            float rmax = -1e30f;
            #pragma unroll
            for (int j = 0; j < 4; j++) {
                const int kg = k0 + tx * 4 + j;
                const float bm = (kg <= qg) ? mk[j] : 0.f;
                float v = s[i][j] * 0.125f;           // / sqrt(64)
                v = v * bm - 1e9f * (1.f - bm);        // exact ref semantics
                s[i][j] = v;
                rmax = fmaxf(rmax, v);
            }
            #pragma unroll
            for (int o = 8; o >= 1; o >>= 1)
                rmax = fmaxf(rmax, __shfl_xor_sync(0xffffffffu, rmax, o));
            const float mnew  = fmaxf(mrun[i], rmax);
            const float alpha = __expf(mrun[i] - mnew);
            mrun[i] = mnew;
            lrun[i] *= alpha;
            #pragma unroll
            for (int j = 0; j < 4; j++) acc[i][j] *= alpha;
            float4 p;
            p.x = __expf(s[i][0] - mnew);
            p.y = __expf(s[i][1] - mnew);
            p.z = __expf(s[i][2] - mnew);
            p.w = __expf(s[i][3] - mnew);
            float psum = p.x + p.y + p.z + p.w;
            #pragma unroll
            for (int o = 8; o >= 1; o >>= 1)
                psum += __shfl_xor_sync(0xffffffffu, psum, o);
            lrun[i] += psum;
            *(float4*)&Ps[ty * 8 + i][tx * 4] = p;
        }
        __syncthreads();  // Ps + V ready

        // acc += P @ V
        #pragma unroll 8
        for (int kk = 0; kk < 64; kk++) {
            const float4 vv = *(const float4*)&KV[kk][tx * 4];
            #pragma unroll
            for (int i = 0; i < 8; i++) {
                const float p = Ps[ty * 8 + i][kk];
                acc[i][0] += p * vv.x;
                acc[i][1] += p * vv.y;
                acc[i][2] += p * vv.z;
                acc[i][3] += p * vv.w;
            }
        }
    }

    // Normalize and write merged-head layout [B*S, D]
    #pragma unroll
    for (int i = 0; i < 8; i++) {
        const float invl = 1.f / lrun[i];
        const int qg = q0 + ty * 8 + i;
        float4 o;
        o.x = acc[i][0] * invl;
        o.y = acc[i][1] * invl;
        o.z = acc[i][2] * invl;
        o.w = acc[i][3] * invl;
        *(float4*)&out[(size_t)(b * 512 + qg) * 1024 + h * 64 + tx * 4] = o;
    }
}

// ---------------------------------------------------------------------------
// Launch: qkv GEMM -> fused attention -> proj GEMM
// ---------------------------------------------------------------------------
extern "C" void kernel_launch(void* const* d_in, const int* in_sizes, int n_in,
                              void* d_out, int out_size)
{
    const float* x        = (const float*)d_in[0];
    const float* mask     = (const float*)d_in[1];
    const float* c_attn_w = (const float*)d_in[2];
    const float* c_attn_b = (const float*)d_in[3];
    const float* c_proj_w = (const float*)d_in[4];
    const float* c_proj_b = (const float*)d_in[5];
    float* out = (float*)d_out;

    float *qkv_ptr = nullptr, *attn_ptr = nullptr;
    cudaGetSymbolAddress((void**)&qkv_ptr, g_qkv);
    cudaGetSymbolAddress((void**)&attn_ptr, g_attn);

    // 1. QKV projection: [4096,1024] @ [1024,3072] + b
    dim3 g1(3072 / 128, 4096 / 128);
    sgemm_bias_kernel<<<g1, 256>>>(x, c_attn_w, c_attn_b, qkv_ptr,
                                   4096, 3072, 1024);

    // 2. Fused causal attention
    dim3 g2(512 / 64, 16, 8);
    attention_kernel<<<g2, 128>>>(qkv_ptr, mask, attn_ptr);

    // 3. Output projection: [4096,1024] @ [1024,1024] + b
    dim3 g3(1024 / 128, 4096 / 128);
    sgemm_bias_kernel<<<g3, 256>>>(attn_ptr, c_proj_w, c_proj_b, out,
                                   4096, 1024, 1024);
}

// round 3
// speedup vs baseline: 1.7465x; 1.7465x over previous
#include <cuda_runtime.h>
#include <cstdint>

// ---------------------------------------------------------------------------
// Scratch (allocation-free: __device__ globals)
// ---------------------------------------------------------------------------
__device__ float g_qkv[8 * 512 * 3072];   // [B*S, 3D] fused qkv output
__device__ float g_attn[8 * 512 * 1024];  // [B*S, D] merged-head attention out

// ---------------------------------------------------------------------------
// TF32 tensor-core GEMM: C[M,N] = A[M,K] @ B[K,N] + bias[N]
// 128x128x32 block tile, 256 threads (8 warps, 2x4), 64x32 warp tile,
// mma.sync.m16n8k8 tf32, cp.async double-buffered smem.
// Requires M%128==0, N%128==0, K%32==0.
// ---------------------------------------------------------------------------
#define GK 32
#define A_STRIDE 36   // 128 rows x (32 + pad) floats: frag banks (4r+c)%32 distinct
#define B_STRIDE 136  // 32 rows x (128 + pad) floats: frag banks (8k+n)%32 distinct
#define STAGE_FLOATS (128 * A_STRIDE + GK * B_STRIDE)  // 8960
#define GEMM_SMEM_BYTES (2 * STAGE_FLOATS * 4)          // 71680

__device__ __forceinline__ uint32_t f2tf(float x) {
    uint32_t r;
    asm("cvt.rna.tf32.f32 %0, %1;" : "=r"(r) : "f"(x));
    return r;
}

__device__ __forceinline__ void mma_tf32(float* c, const uint32_t* a,
                                         const uint32_t* b) {
    asm volatile(
        "mma.sync.aligned.m16n8k8.row.col.f32.tf32.tf32.f32 "
        "{%0,%1,%2,%3}, {%4,%5,%6,%7}, {%8,%9}, {%0,%1,%2,%3};"
        : "+f"(c[0]), "+f"(c[1]), "+f"(c[2]), "+f"(c[3])
        : "r"(a[0]), "r"(a[1]), "r"(a[2]), "r"(a[3]), "r"(b[0]), "r"(b[1]));
}

__device__ __forceinline__ void cp_async16(uint32_t s, const void* g) {
    asm volatile("cp.async.cg.shared.global [%0], [%1], 16;\n"
                 :: "r"(s), "l"(g) : "memory");
}

__global__ void __launch_bounds__(256) gemm_tf32_kernel(
    const float* __restrict__ A, const float* __restrict__ B,
    const float* __restrict__ bias, float* __restrict__ C,
    int M, int N, int K)
{
    extern __shared__ float smem[];
    const int tid  = threadIdx.x;
    const int lane = tid & 31;
    const int warp = tid >> 5;
    const int wm   = warp >> 2;   // 0..1  (64 rows each)
    const int wn   = warp & 3;    // 0..3  (32 cols each)
    const int bx   = blockIdx.x;
    const int by   = blockIdx.y;

    // cp.async source/dest indexing (16 floats per thread per tile)
    const int arow = tid >> 1;            // 0..127
    const int acol = (tid & 1) << 4;      // 0 or 16
    const int brow = tid >> 3;            // 0..31
    const int bcol = (tid & 7) << 4;      // 0..112

    const float* Ag = A + (size_t)(by * 128 + arow) * K + acol;
    const float* Bg = B + (size_t)brow * N + bx * 128 + bcol;

    auto load_tile = [&](int stage, int k0) {
        float* As = smem + stage * STAGE_FLOATS;
        float* Bs = As + 128 * A_STRIDE;
        uint32_t as_addr =
            (uint32_t)__cvta_generic_to_shared(&As[arow * A_STRIDE + acol]);
        const float* ag = Ag + k0;
        #pragma unroll
        for (int c = 0; c < 4; c++)
            cp_async16(as_addr + c * 16, ag + c * 4);
        uint32_t bs_addr =
            (uint32_t)__cvta_generic_to_shared(&Bs[brow * B_STRIDE + bcol]);
        const float* bg = Bg + (size_t)k0 * N;
        #pragma unroll
        for (int c = 0; c < 4; c++)
            cp_async16(bs_addr + c * 16, bg + c * 4);
    };

    float acc[4][4][4];
    #pragma unroll
    for (int i = 0; i < 4; i++)
        #pragma unroll
        for (int j = 0; j < 4; j++)
            #pragma unroll
            for (int r = 0; r < 4; r++) acc[i][j][r] = 0.f;

    load_tile(0, 0);
    asm volatile("cp.async.commit_group;" ::: "memory");
    load_tile(1, GK);
    asm volatile("cp.async.commit_group;" ::: "memory");

    const int niter = K / GK;
    const int r0 = lane >> 2;    // 0..7
    const int c0 = lane & 3;     // 0..3

    for (int it = 0; it < niter; it++) {
        asm volatile("cp.async.wait_group 1;" ::: "memory");
        __syncthreads();

        const float* As = smem + (it & 1) * STAGE_FLOATS;
        const float* Bs = As + 128 * A_STRIDE;

        #pragma unroll
        for (int ks = 0; ks < 4; ks++) {
            uint32_t af[4][4], bf[4][2];
            #pragma unroll
            for (int i = 0; i < 4; i++) {
                const float* ap =
                    As + (wm * 64 + i * 16 + r0) * A_STRIDE + ks * 8 + c0;
                af[i][0] = f2tf(ap[0]);
                af[i][1] = f2tf(ap[8 * A_STRIDE]);
                af[i][2] = f2tf(ap[4]);
                af[i][3] = f2tf(ap[8 * A_STRIDE + 4]);
            }
            #pragma unroll
            for (int j = 0; j < 4; j++) {
                const float* bp =
                    Bs + (ks * 8 + c0) * B_STRIDE + wn * 32 + j * 8 + r0;
                bf[j][0] = f2tf(bp[0]);
                bf[j][1] = f2tf(bp[4 * B_STRIDE]);
            }
            #pragma unroll
            for (int i = 0; i < 4; i++)
                #pragma unroll
                for (int j = 0; j < 4; j++)
                    mma_tf32(acc[i][j], af[i], bf[j]);
        }
        __syncthreads();

        const int nk = (it + 2) * GK;
        if (nk < K) load_tile(it & 1, nk);
        asm volatile("cp.async.commit_group;" ::: "memory");
    }

    // Epilogue: add bias, write C (float2 per fragment row)
    #pragma unroll
    for (int i = 0; i < 4; i++) {
        const int row0 = by * 128 + wm * 64 + i * 16 + r0;
        #pragma unroll
        for (int j = 0; j < 4; j++) {
            const int col = bx * 128 + wn * 32 + j * 8 + 2 * c0;
            const float2 bv = *(const float2*)&bias[col];
            float2 o0, o1;
            o0.x = acc[i][j][0] + bv.x;
            o0.y = acc[i][j][1] + bv.y;
            o1.x = acc[i][j][2] + bv.x;
            o1.y = acc[i][j][3] + bv.y;
            *(float2*)&C[(size_t)row0 * N + col] = o0;
            *(float2*)&C[(size_t)(row0 + 8) * N + col] = o1;
        }
    }
}

// ---------------------------------------------------------------------------
// Fused causal attention (flash-style online softmax), fp32.
// grid = (S/64, H, B); 128 threads; 64-query tile per block.
// ---------------------------------------------------------------------------
__global__ void __launch_bounds__(128) attention_kernel(
    const float* __restrict__ qkv, const float* __restrict__ mask,
    float* __restrict__ out)
{
    const int qt  = blockIdx.x;
    const int h   = blockIdx.y;
    const int b   = blockIdx.z;
    const int tid = threadIdx.x;
    const int tx  = tid & 15;
    const int ty  = tid >> 4;

    __shared__ float Qt[64][64];
    __shared__ float KV[64][64];
    __shared__ float Ps[64][64];

    const int q0 = qt * 64;
    const float* qbase = qkv + (size_t)(b * 512) * 3072 + h * 64;
    const float* kbase = qbase + 1024;
    const float* vbase = qbase + 2048;

    for (int t = tid; t < 64 * 16; t += 128) {
        const int r = t >> 4;
        const int c = (t & 15) << 2;
        float4 v = *(const float4*)(qbase + (size_t)(q0 + r) * 3072 + c);
        Qt[c + 0][r] = v.x; Qt[c + 1][r] = v.y;
        Qt[c + 2][r] = v.z; Qt[c + 3][r] = v.w;
    }

    float acc[8][4];
    float mrun[8], lrun[8];
    #pragma unroll
    for (int i = 0; i < 8; i++) {
        mrun[i] = -1e30f;
        lrun[i] = 0.f;
        #pragma unroll
        for (int j = 0; j < 4; j++) acc[i][j] = 0.f;
    }

    for (int kt = 0; kt <= qt; kt++) {
        const int k0 = kt * 64;

        __syncthreads();
        for (int t = tid; t < 64 * 16; t += 128) {
            const int r = t >> 4;
            const int c = (t & 15) << 2;
            float4 v = *(const float4*)(kbase + (size_t)(k0 + r) * 3072 + c);
            KV[c + 0][r] = v.x; KV[c + 1][r] = v.y;
            KV[c + 2][r] = v.z; KV[c + 3][r] = v.w;
        }
        __syncthreads();

        float s[8][4];
        #pragma unroll
        for (int i = 0; i < 8; i++)
            #pragma unroll
            for (int j = 0; j < 4; j++) s[i][j] = 0.f;

        #pragma unroll 8
        for (int d = 0; d < 64; d++) {
            float qr[8];
            *(float4*)&qr[0] = *(const float4*)&Qt[d][ty * 8];
            *(float4*)&qr[4] = *(const float4*)&Qt[d][ty * 8 + 4];
            const float4 kv = *(const float4*)&KV[d][tx * 4];
            #pragma unroll
            for (int i = 0; i < 8; i++) {
                s[i][0] += qr[i] * kv.x;
                s[i][1] += qr[i] * kv.y;
                s[i][2] += qr[i] * kv.z;
                s[i][3] += qr[i] * kv.w;
            }
        }
        __syncthreads();

        for (int t = tid; t < 64 * 16; t += 128) {
            const int r = t >> 4;
            const int c = (t & 15) << 2;
            *(float4*)&KV[r][c] =
                *(const float4*)(vbase + (size_t)(k0 + r) * 3072 + c);
        }

        float mk[4];
        #pragma unroll
        for (int j = 0; j < 4; j++)
            mk[j] = mask[b * 512 + k0 + tx * 4 + j];

        #pragma unroll
        for (int i = 0; i < 8; i++) {
            const int qg = q0 + ty * 8 + i;
            float rmax = -1e30f;
            #pragma unroll
            for (int j = 0; j < 4; j++) {
                const int kg = k0 + tx * 4 + j;
                const float bm = (kg <= qg) ? mk[j] : 0.f;
                float v = s[i][j] * 0.125f;
                v = v * bm - 1e9f * (1.f - bm);
                s[i][j] = v;
                rmax = fmaxf(rmax, v);
            }
            #pragma unroll
            for (int o = 8; o >= 1; o >>= 1)
                rmax = fmaxf(rmax, __shfl_xor_sync(0xffffffffu, rmax, o));
            const float mnew  = fmaxf(mrun[i], rmax);
            const float alpha = __expf(mrun[i] - mnew);
            mrun[i] = mnew;
            lrun[i] *= alpha;
            #pragma unroll
            for (int j = 0; j < 4; j++) acc[i][j] *= alpha;
            float4 p;
            p.x = __expf(s[i][0] - mnew);
            p.y = __expf(s[i][1] - mnew);
            p.z = __expf(s[i][2] - mnew);
            p.w = __expf(s[i][3] - mnew);
            float psum = p.x + p.y + p.z + p.w;
            #pragma unroll
            for (int o = 8; o >= 1; o >>= 1)
                psum += __shfl_xor_sync(0xffffffffu, psum, o);
            lrun[i] += psum;
            *(float4*)&Ps[ty * 8 + i][tx * 4] = p;
        }
        __syncthreads();

        #pragma unroll 8
        for (int kk = 0; kk < 64; kk++) {
            const float4 vv = *(const float4*)&KV[kk][tx * 4];
            #pragma unroll
            for (int i = 0; i < 8; i++) {
                const float p = Ps[ty * 8 + i][kk];
                acc[i][0] += p * vv.x;
                acc[i][1] += p * vv.y;
                acc[i][2] += p * vv.z;
                acc[i][3] += p * vv.w;
            }
        }
    }

    #pragma unroll
    for (int i = 0; i < 8; i++) {
        const float invl = 1.f / lrun[i];
        const int qg = q0 + ty * 8 + i;
        float4 o;
        o.x = acc[i][0] * invl;
        o.y = acc[i][1] * invl;
        o.z = acc[i][2] * invl;
        o.w = acc[i][3] * invl;
        *(float4*)&out[(size_t)(b * 512 + qg) * 1024 + h * 64 + tx * 4] = o;
    }
}

// ---------------------------------------------------------------------------
// Launch: qkv GEMM (tf32) -> fused attention -> proj GEMM (tf32)
// ---------------------------------------------------------------------------
extern "C" void kernel_launch(void* const* d_in, const int* in_sizes, int n_in,
                              void* d_out, int out_size)
{
    const float* x        = (const float*)d_in[0];
    const float* mask     = (const float*)d_in[1];
    const float* c_attn_w = (const float*)d_in[2];
    const float* c_attn_b = (const float*)d_in[3];
    const float* c_proj_w = (const float*)d_in[4];
    const float* c_proj_b = (const float*)d_in[5];
    float* out = (float*)d_out;

    float *qkv_ptr = nullptr, *attn_ptr = nullptr;
    cudaGetSymbolAddress((void**)&qkv_ptr, g_qkv);
    cudaGetSymbolAddress((void**)&attn_ptr, g_attn);

    cudaFuncSetAttribute(gemm_tf32_kernel,
                         cudaFuncAttributeMaxDynamicSharedMemorySize,
                         GEMM_SMEM_BYTES);

    // 1. QKV projection: [4096,1024] @ [1024,3072] + b
    dim3 g1(3072 / 128, 4096 / 128);
    gemm_tf32_kernel<<<g1, 256, GEMM_SMEM_BYTES>>>(x, c_attn_w, c_attn_b,
                                                   qkv_ptr, 4096, 3072, 1024);

    // 2. Fused causal attention
    dim3 g2(512 / 64, 16, 8);
    attention_kernel<<<g2, 128>>>(qkv_ptr, mask, attn_ptr);

    // 3. Output projection: [4096,1024] @ [1024,1024] + b
    dim3 g3(1024 / 128, 4096 / 128);
    gemm_tf32_kernel<<<g3, 256, GEMM_SMEM_BYTES>>>(attn_ptr, c_proj_w,
                                                   c_proj_b, out,
                                                   4096, 1024, 1024);
}